// round 1
// baseline (speedup 1.0000x reference)
#include <cuda_runtime.h>
#include <cstdint>

// Problem constants (fixed by the reference)
#define B_  1024
#define S_  200
#define H_  128
#define N_  100000
#define M_  (B_ * S_)   // 204800

// Scratch (no allocations allowed)
__device__ float g_lm[B_ * H_];      // Wr @ last_memory  [B,H]
__device__ float g_scores[M_];       // pre-softmax scores [B*S]

// ---------------------------------------------------------------------------
// Kernel 1: lm[b,k] = dot(Wr[k,:], last_memory[b,:])
// grid = B, block = 128 (thread k)
// ---------------------------------------------------------------------------
__global__ void lm_kernel(const float* __restrict__ last_memory,
                          const float* __restrict__ Wr) {
    __shared__ float lastm[H_];
    int b = blockIdx.x;
    int t = threadIdx.x;
    lastm[t] = last_memory[b * H_ + t];
    __syncthreads();

    const float4* wr4 = reinterpret_cast<const float4*>(Wr + t * H_);
    const float4* lm4 = reinterpret_cast<const float4*>(lastm);
    float acc = 0.f;
#pragma unroll
    for (int h4 = 0; h4 < H_ / 4; h4++) {
        float4 w = wr4[h4];
        float4 x = lm4[h4];
        acc += w.x * x.x + w.y * x.y + w.z * x.z + w.w * x.w;
    }
    g_lm[b * H_ + t] = acc;
}

// ---------------------------------------------------------------------------
// Kernel 2: fused GEMM + tanh + Vr-dot
//   scores[m] = sum_k Vr[k]*tanh( dot(A[m,:],Ur[k,:]) + lm[b(m),k] ) + Vr_b
// Tile: BM=128 rows x BN=128 cols (all of H), BK=32, 256 threads, 8x8/thread.
// ---------------------------------------------------------------------------
#define BM 128
#define BN 128
#define BK 32

__global__ __launch_bounds__(256, 2)
void gemm_score_kernel(const float* __restrict__ A,     // [M,128]
                       const float* __restrict__ Ur,    // [128,128]
                       const float* __restrict__ Vr,    // [128]
                       const float* __restrict__ Vrb) { // [1]
    __shared__ float sA[BK][BM + 4];  // transposed: sA[k][row]
    __shared__ float sB[BK][BN + 4];  // transposed: sB[k][col]

    const int tid = threadIdx.x;
    const int tx  = tid & 15;          // col group (8 cols each)
    const int ty  = tid >> 4;          // row group (8 rows each)
    const int m0  = blockIdx.x * BM;

    float acc[8][8];
#pragma unroll
    for (int i = 0; i < 8; i++)
#pragma unroll
        for (int j = 0; j < 8; j++) acc[i][j] = 0.f;

    const int f4    = tid & 7;   // which float4 within the 32-col K-chunk
    const int rbase = tid >> 3;  // 0..31

    for (int h0 = 0; h0 < H_; h0 += BK) {
        // Load A tile: 128 rows x 32 K, store transposed
#pragma unroll
        for (int p = 0; p < 4; p++) {
            int r = rbase + p * 32;
            float4 v = *reinterpret_cast<const float4*>(
                A + (size_t)(m0 + r) * H_ + h0 + f4 * 4);
            sA[f4 * 4 + 0][r] = v.x;
            sA[f4 * 4 + 1][r] = v.y;
            sA[f4 * 4 + 2][r] = v.z;
            sA[f4 * 4 + 3][r] = v.w;
        }
        // Load Ur tile: 128 k-rows x 32 K, store transposed
#pragma unroll
        for (int p = 0; p < 4; p++) {
            int c = rbase + p * 32;
            float4 v = *reinterpret_cast<const float4*>(
                Ur + (size_t)c * H_ + h0 + f4 * 4);
            sB[f4 * 4 + 0][c] = v.x;
            sB[f4 * 4 + 1][c] = v.y;
            sB[f4 * 4 + 2][c] = v.z;
            sB[f4 * 4 + 3][c] = v.w;
        }
        __syncthreads();

#pragma unroll 4
        for (int kk = 0; kk < BK; kk++) {
            float afr[8], bfr[8];
            *reinterpret_cast<float4*>(&afr[0]) =
                *reinterpret_cast<const float4*>(&sA[kk][ty * 8]);
            *reinterpret_cast<float4*>(&afr[4]) =
                *reinterpret_cast<const float4*>(&sA[kk][ty * 8 + 4]);
            *reinterpret_cast<float4*>(&bfr[0]) =
                *reinterpret_cast<const float4*>(&sB[kk][tx * 8]);
            *reinterpret_cast<float4*>(&bfr[4]) =
                *reinterpret_cast<const float4*>(&sB[kk][tx * 8 + 4]);
#pragma unroll
            for (int i = 0; i < 8; i++)
#pragma unroll
                for (int j = 0; j < 8; j++)
                    acc[i][j] += afr[i] * bfr[j];
        }
        __syncthreads();
    }

    // Epilogue: tanh(acc + lm) * Vr, row-reduce, write scores
    float vfr[8];
    *reinterpret_cast<float4*>(&vfr[0]) =
        *reinterpret_cast<const float4*>(Vr + tx * 8);
    *reinterpret_cast<float4*>(&vfr[4]) =
        *reinterpret_cast<const float4*>(Vr + tx * 8 + 4);
    const float vb = Vrb[0];

#pragma unroll
    for (int i = 0; i < 8; i++) {
        int m = m0 + ty * 8 + i;
        int b = m / S_;
        const float* lmrow = g_lm + (size_t)b * H_;
        float lfr[8];
        *reinterpret_cast<float4*>(&lfr[0]) =
            *reinterpret_cast<const float4*>(lmrow + tx * 8);
        *reinterpret_cast<float4*>(&lfr[4]) =
            *reinterpret_cast<const float4*>(lmrow + tx * 8 + 4);
        float p = 0.f;
#pragma unroll
        for (int j = 0; j < 8; j++)
            p += tanhf(acc[i][j] + lfr[j]) * vfr[j];
        // reduce over the 16 col-groups (lanes with same ty share a 16-lane segment)
#pragma unroll
        for (int off = 8; off > 0; off >>= 1)
            p += __shfl_down_sync(0xffffffffu, p, off, 16);
        if (tx == 0) g_scores[m] = p + vb;
    }
}

// ---------------------------------------------------------------------------
// Kernel 3: per-batch-row: zero out row, softmax over S, scatter-add.
// grid = B, block = 256
// ---------------------------------------------------------------------------
__global__ void softmax_scatter_kernel(const int* __restrict__ item_seq,
                                       const unsigned char* __restrict__ mask,
                                       float* __restrict__ out) {
    const int b   = blockIdx.x;
    const int tid = threadIdx.x;

    // 1) zero this batch row of out (100000 floats = 25000 float4)
    float4* orow = reinterpret_cast<float4*>(out + (size_t)b * N_);
    const float4 z4 = make_float4(0.f, 0.f, 0.f, 0.f);
    for (int i = tid; i < N_ / 4; i += 256) orow[i] = z4;

    // 2) softmax over S=200
    __shared__ float sc[256];
    float myv = -3.0e38f;
    if (tid < S_) {
        myv = g_scores[(size_t)b * S_ + tid];
        if (mask[(size_t)b * S_ + tid]) myv = -1e9f;
    }
    sc[tid] = myv;
    __syncthreads();
#pragma unroll
    for (int s = 128; s > 0; s >>= 1) {
        if (tid < s) sc[tid] = fmaxf(sc[tid], sc[tid + s]);
        __syncthreads();
    }
    const float mx = sc[0];
    __syncthreads();

    float e = (tid < S_) ? expf(myv - mx) : 0.f;
    sc[tid] = e;
    __syncthreads();
#pragma unroll
    for (int s = 128; s > 0; s >>= 1) {
        if (tid < s) sc[tid] += sc[tid + s];
        __syncthreads();
    }
    const float inv = 1.0f / sc[0];

    // 3) scatter (this block's prior global zero-stores are visible after the
    //    __syncthreads above; all targets are inside this block's own row)
    if (tid < S_) {
        int item = item_seq[(size_t)b * S_ + tid];
        atomicAdd(out + (size_t)b * N_ + item, e * inv);
    }
}

// ---------------------------------------------------------------------------
extern "C" void kernel_launch(void* const* d_in, const int* in_sizes, int n_in,
                              void* d_out, int out_size) {
    const float*         all_memory  = (const float*)d_in[0];
    const float*         last_memory = (const float*)d_in[1];
    const int*           item_seq    = (const int*)d_in[2];
    const unsigned char* mask        = (const unsigned char*)d_in[3];
    const float*         Ur_w        = (const float*)d_in[4];
    const float*         Wr_w        = (const float*)d_in[5];
    const float*         Vr_w        = (const float*)d_in[6];
    const float*         Vr_b        = (const float*)d_in[7];
    float*               out         = (float*)d_out;

    lm_kernel<<<B_, H_>>>(last_memory, Wr_w);
    gemm_score_kernel<<<M_ / BM, 256>>>(all_memory, Ur_w, Vr_w, Vr_b);
    softmax_scatter_kernel<<<B_, 256>>>(item_seq, mask, out);
}

// round 6
// speedup vs baseline: 1.2973x; 1.2973x over previous
#include <cuda_runtime.h>
#include <cuda_bf16.h>
#include <cstdint>

// Problem constants (fixed by the reference)
#define B_  1024
#define S_  200
#define H_  128
#define N_  100000
#define M_  (B_ * S_)   // 204800

#define RSB 272                   // padded row stride in bytes (128 bf16 = 256B + 16B pad)
#define TILE_BYTES (128 * RSB)    // 34816

// Scratch (no allocations allowed)
__device__ float g_lm[B_ * H_];                           // Wr @ last_memory [B,H]
__device__ float g_scores[M_];                            // pre-softmax scores
__device__ __align__(16) unsigned char g_urh[TILE_BYTES]; // Ur hi bf16, padded rows
__device__ __align__(16) unsigned char g_url[TILE_BYTES]; // Ur lo bf16

// ---------------------------------------------------------------------------
// Helpers
// ---------------------------------------------------------------------------
__device__ __forceinline__ uint32_t smem_u32(const void* p) {
    uint32_t a;
    asm("{ .reg .u64 t; cvta.to.shared.u64 t, %1; cvt.u32.u64 %0, t; }" : "=r"(a) : "l"(p));
    return a;
}

__device__ __forceinline__ void ldsm4(uint32_t* r, uint32_t addr) {
    asm volatile("ldmatrix.sync.aligned.m8n8.x4.shared.b16 {%0,%1,%2,%3}, [%4];"
                 : "=r"(r[0]), "=r"(r[1]), "=r"(r[2]), "=r"(r[3]) : "r"(addr));
}

__device__ __forceinline__ void mma16816(float* c, const uint32_t* a,
                                         uint32_t b0, uint32_t b1) {
    asm volatile(
        "mma.sync.aligned.m16n8k16.row.col.f32.bf16.bf16.f32 "
        "{%0,%1,%2,%3}, {%4,%5,%6,%7}, {%8,%9}, {%0,%1,%2,%3};"
        : "+f"(c[0]), "+f"(c[1]), "+f"(c[2]), "+f"(c[3])
        : "r"(a[0]), "r"(a[1]), "r"(a[2]), "r"(a[3]), "r"(b0), "r"(b1));
}

// hi/lo bf16 split of a float4
__device__ __forceinline__ void split4(float4 v,
                                       __nv_bfloat162& h01, __nv_bfloat162& h23,
                                       __nv_bfloat162& l01, __nv_bfloat162& l23) {
    h01.x = __float2bfloat16(v.x); h01.y = __float2bfloat16(v.y);
    h23.x = __float2bfloat16(v.z); h23.y = __float2bfloat16(v.w);
    l01.x = __float2bfloat16(v.x - __bfloat162float(h01.x));
    l01.y = __float2bfloat16(v.y - __bfloat162float(h01.y));
    l23.x = __float2bfloat16(v.z - __bfloat162float(h23.x));
    l23.y = __float2bfloat16(v.w - __bfloat162float(h23.y));
}

// ---------------------------------------------------------------------------
// Kernel 0: split Ur [128,128] f32 into bf16 hi/lo, padded-272B rows.
// ---------------------------------------------------------------------------
__global__ void prep_ur_kernel(const float* __restrict__ Ur) {
    int row = threadIdx.x;
    const float4* src = reinterpret_cast<const float4*>(Ur + row * H_);
    unsigned char* dh = g_urh + row * RSB;
    unsigned char* dl = g_url + row * RSB;
#pragma unroll
    for (int i = 0; i < 32; i++) {
        float4 v = src[i];
        __nv_bfloat162 h01, h23, l01, l23;
        split4(v, h01, h23, l01, l23);
        *reinterpret_cast<__nv_bfloat162*>(dh + i * 8)     = h01;
        *reinterpret_cast<__nv_bfloat162*>(dh + i * 8 + 4) = h23;
        *reinterpret_cast<__nv_bfloat162*>(dl + i * 8)     = l01;
        *reinterpret_cast<__nv_bfloat162*>(dl + i * 8 + 4) = l23;
    }
}

// ---------------------------------------------------------------------------
// Kernel 1: lm[b,k] = dot(Wr[k,:], last_memory[b,:])
// ---------------------------------------------------------------------------
__global__ void lm_kernel(const float* __restrict__ last_memory,
                          const float* __restrict__ Wr) {
    __shared__ float lastm[H_];
    int b = blockIdx.x;
    int t = threadIdx.x;
    lastm[t] = last_memory[b * H_ + t];
    __syncthreads();

    const float4* wr4 = reinterpret_cast<const float4*>(Wr + t * H_);
    const float4* lm4 = reinterpret_cast<const float4*>(lastm);
    float a0 = 0.f, a1 = 0.f, a2 = 0.f, a3 = 0.f;
#pragma unroll
    for (int i = 0; i < 32; i += 4) {
        float4 w0 = wr4[i], w1 = wr4[i + 1], w2 = wr4[i + 2], w3 = wr4[i + 3];
        float4 x0 = lm4[i], x1 = lm4[i + 1], x2 = lm4[i + 2], x3 = lm4[i + 3];
        a0 += w0.x * x0.x + w0.y * x0.y + w0.z * x0.z + w0.w * x0.w;
        a1 += w1.x * x1.x + w1.y * x1.y + w1.z * x1.z + w1.w * x1.w;
        a2 += w2.x * x2.x + w2.y * x2.y + w2.z * x2.z + w2.w * x2.w;
        a3 += w3.x * x3.x + w3.y * x3.y + w3.z * x3.z + w3.w * x3.w;
    }
    g_lm[b * H_ + t] = (a0 + a1) + (a2 + a3);
}

// ---------------------------------------------------------------------------
// Kernel 2: mma.sync bf16-split GEMM + tanh + Vr-dot epilogue
//           + fused streaming zero of d_out (overlaps DRAM with tensor pipe).
// CTA = 128 rows x 128 cols. 8 warps: warp (wm in {0,1}, wn in {0..3}).
// D = Ahi*Bhi + Ahi*Blo + Alo*Bhi (fp32 acc in registers).
// ---------------------------------------------------------------------------
#define SM_AH 0
#define SM_AL TILE_BYTES
#define SM_BH (2 * TILE_BYTES)
#define SM_BL (3 * TILE_BYTES)
#define SM_VR (4 * TILE_BYTES)            // 512 B
#define SM_LM (SM_VR + 512)               // 1024 B
#define SM_PT (SM_LM + 1024)              // 512 B
#define SMEM_TOTAL (SM_PT + 512)          // 141312 B

#define ZERO_TOTAL4 (B_ * N_ / 4)         // 25,600,000 float4
#define ZERO_PER_CTA 16000                // ZERO_TOTAL4 / 1600 CTAs

__global__ __launch_bounds__(256, 1)
void gemm_score_mma(const float* __restrict__ A,
                    const float* __restrict__ Vr,
                    const float* __restrict__ Vrb,
                    float* __restrict__ out) {
    extern __shared__ __align__(16) unsigned char smem[];
    const int tid  = threadIdx.x;
    const int lane = tid & 31;
    const int w    = tid >> 5;
    const int wm   = w & 1;
    const int wn   = w >> 1;
    const int m0   = blockIdx.x * 128;
    const int b0   = m0 / S_;
    const int b1   = (m0 + 127) / S_;

    // --- fused zero of d_out slice: streaming stores, issued first so the
    //     DRAM write drains under the MMA compute phase ---
    {
        float4* o4 = reinterpret_cast<float4*>(out);
        const size_t base = (size_t)blockIdx.x * ZERO_PER_CTA;
        const float4 z4 = make_float4(0.f, 0.f, 0.f, 0.f);
#pragma unroll 4
        for (int i = tid; i < ZERO_PER_CTA; i += 256)
            __stcs(o4 + base + i, z4);
    }

    float* sVr = reinterpret_cast<float*>(smem + SM_VR);
    float* sLm = reinterpret_cast<float*>(smem + SM_LM);
    float* sPt = reinterpret_cast<float*>(smem + SM_PT);

    // --- copy pre-split Ur into smem ---
    {
        const uint4* sH = reinterpret_cast<const uint4*>(g_urh);
        const uint4* sL = reinterpret_cast<const uint4*>(g_url);
        uint4* dH = reinterpret_cast<uint4*>(smem + SM_BH);
        uint4* dL = reinterpret_cast<uint4*>(smem + SM_BL);
#pragma unroll
        for (int i = tid; i < TILE_BYTES / 16; i += 256) { dH[i] = sH[i]; dL[i] = sL[i]; }
    }

    // --- load + split A tile (row stride RSB=272B; 128 bf16 = 256B payload) ---
    {
        int row = tid >> 1, half = tid & 1;
        const float4* src = reinterpret_cast<const float4*>(
            A + (size_t)(m0 + row) * H_ + half * 64);
        unsigned char* ah = smem + SM_AH + row * RSB + half * 128;
        unsigned char* al = smem + SM_AL + row * RSB + half * 128;
#pragma unroll
        for (int i = 0; i < 16; i++) {
            float4 v = src[i];
            __nv_bfloat162 h01, h23, l01, l23;
            split4(v, h01, h23, l01, l23);
            *reinterpret_cast<__nv_bfloat162*>(ah + i * 8)     = h01;
            *reinterpret_cast<__nv_bfloat162*>(ah + i * 8 + 4) = h23;
            *reinterpret_cast<__nv_bfloat162*>(al + i * 8)     = l01;
            *reinterpret_cast<__nv_bfloat162*>(al + i * 8 + 4) = l23;
        }
    }

    // --- Vr, lm rows, partial buffer ---
    if (tid < 128) { sVr[tid] = Vr[tid]; sPt[tid] = 0.f; }
    {
        int sel = tid >> 7, col = tid & 127;
        sLm[sel * 128 + col] = g_lm[(sel ? b1 : b0) * H_ + col];
    }
    __syncthreads();

    // --- per-lane ldmatrix base addresses ---
    const uint32_t sb = smem_u32(smem);
    // A x4: lanes 0-15 -> rows 0..15 @k, lanes 16-31 -> same rows @k+8 (16B)
    const uint32_t aRow = (uint32_t)(wm * 64 + (lane & 15)) * RSB + ((lane >> 4) << 4);
    // B x4: lane groups of 8 -> (n0-7,k0), (n0-7,k8), (n8-15,k0), (n8-15,k8)
    const uint32_t bRow = (uint32_t)(wn * 32 + (lane & 7) + ((lane >> 4) << 3)) * RSB +
                          (((lane >> 3) & 1) << 4);
    const uint32_t aH = sb + SM_AH + aRow;
    const uint32_t aL = sb + SM_AL + aRow;
    const uint32_t bH = sb + SM_BH + bRow;
    const uint32_t bL = sb + SM_BL + bRow;

    float acc[4][4][4];
#pragma unroll
    for (int i = 0; i < 4; i++)
#pragma unroll
        for (int j = 0; j < 4; j++)
#pragma unroll
            for (int k = 0; k < 4; k++) acc[i][j][k] = 0.f;

#pragma unroll
    for (int ks = 0; ks < 8; ks++) {
        const uint32_t ko = ks * 32;  // 16 k-elems = 32 bytes
        uint32_t bh[8], bl[8];
        ldsm4(&bh[0], bH + ko);                 // n-tiles 0,1
        ldsm4(&bh[4], bH + 16 * RSB + ko);      // n-tiles 2,3
        ldsm4(&bl[0], bL + ko);
        ldsm4(&bl[4], bL + 16 * RSB + ko);
#pragma unroll
        for (int mh = 0; mh < 2; mh++) {
            uint32_t ah[8], al[8];
            ldsm4(&ah[0], aH + (mh * 2) * 16 * RSB + ko);
            ldsm4(&ah[4], aH + (mh * 2 + 1) * 16 * RSB + ko);
            ldsm4(&al[0], aL + (mh * 2) * 16 * RSB + ko);
            ldsm4(&al[4], aL + (mh * 2 + 1) * 16 * RSB + ko);
#pragma unroll
            for (int i = 0; i < 2; i++) {
                const int mt = mh * 2 + i;
#pragma unroll
                for (int nt = 0; nt < 4; nt++) {
                    mma16816(acc[mt][nt], &ah[i * 4], bh[nt * 2], bh[nt * 2 + 1]);
                    mma16816(acc[mt][nt], &ah[i * 4], bl[nt * 2], bl[nt * 2 + 1]);
                    mma16816(acc[mt][nt], &al[i * 4], bh[nt * 2], bh[nt * 2 + 1]);
                }
            }
        }
    }

    // --- epilogue: tanh(acc+lm)*Vr, reduce over cols -> sPt[row] ---
#pragma unroll
    for (int mt = 0; mt < 4; mt++) {
#pragma unroll
        for (int h = 0; h < 2; h++) {
            const int r = wm * 64 + mt * 16 + (lane >> 2) + h * 8;
            const float* lmrow = sLm + (((m0 + r) / S_ != b0) ? 128 : 0);
            float p = 0.f;
#pragma unroll
            for (int nt = 0; nt < 4; nt++) {
#pragma unroll
                for (int j = 0; j < 2; j++) {
                    const int c = wn * 32 + nt * 8 + 2 * (lane & 3) + j;
                    p += tanhf(acc[mt][nt][h * 2 + j] + lmrow[c]) * sVr[c];
                }
            }
            p += __shfl_xor_sync(0xffffffffu, p, 1);
            p += __shfl_xor_sync(0xffffffffu, p, 2);
            if ((lane & 3) == 0) atomicAdd(&sPt[r], p);
        }
    }
    __syncthreads();
    if (tid < 128) g_scores[m0 + tid] = sPt[tid] + __ldg(Vrb);
}

// ---------------------------------------------------------------------------
// Kernel 3: per-batch-row softmax over S + scatter-add (out pre-zeroed by
// the gemm kernel; cross-kernel ordering guarantees visibility).
// ---------------------------------------------------------------------------
__global__ void softmax_scatter_kernel(const int* __restrict__ item_seq,
                                       const unsigned char* __restrict__ mask,
                                       float* __restrict__ out) {
    const int b   = blockIdx.x;
    const int tid = threadIdx.x;

    __shared__ float sc[256];
    float myv = -3.0e38f;
    if (tid < S_) {
        myv = g_scores[(size_t)b * S_ + tid];
        if (mask[(size_t)b * S_ + tid]) myv = -1e9f;
    }
    sc[tid] = myv;
    __syncthreads();
#pragma unroll
    for (int s = 128; s > 0; s >>= 1) {
        if (tid < s) sc[tid] = fmaxf(sc[tid], sc[tid + s]);
        __syncthreads();
    }
    const float mx = sc[0];
    __syncthreads();

    float e = (tid < S_) ? expf(myv - mx) : 0.f;
    sc[tid] = e;
    __syncthreads();
#pragma unroll
    for (int s = 128; s > 0; s >>= 1) {
        if (tid < s) sc[tid] += sc[tid + s];
        __syncthreads();
    }
    const float inv = 1.0f / sc[0];

    if (tid < S_) {
        int item = item_seq[(size_t)b * S_ + tid];
        atomicAdd(out + (size_t)b * N_ + item, e * inv);
    }
}

// ---------------------------------------------------------------------------
extern "C" void kernel_launch(void* const* d_in, const int* in_sizes, int n_in,
                              void* d_out, int out_size) {
    const float*         all_memory  = (const float*)d_in[0];
    const float*         last_memory = (const float*)d_in[1];
    const int*           item_seq    = (const int*)d_in[2];
    const unsigned char* mask        = (const unsigned char*)d_in[3];
    const float*         Ur_w        = (const float*)d_in[4];
    const float*         Wr_w        = (const float*)d_in[5];
    const float*         Vr_w        = (const float*)d_in[6];
    const float*         Vr_b        = (const float*)d_in[7];
    float*               out         = (float*)d_out;

    cudaFuncSetAttribute(gemm_score_mma,
                         cudaFuncAttributeMaxDynamicSharedMemorySize, SMEM_TOTAL);

    prep_ur_kernel<<<1, 128>>>(Ur_w);
    lm_kernel<<<B_, H_>>>(last_memory, Wr_w);
    gemm_score_mma<<<M_ / 128, 256, SMEM_TOTAL>>>(all_memory, Vr_w, Vr_b, out);
    softmax_scatter_kernel<<<B_, 256>>>(item_seq, mask, out);
}